// round 14
// baseline (speedup 1.0000x reference)
#include <cuda_runtime.h>
#include <cuda_bf16.h>
#include <cstdint>
#include <cstddef>

#define NN      10000
#define INDIM   128
#define HID     256
#define EMBD    128
#define RR      8
#define CC      32
#define EE      640000
#define KSPLIT  11
#define NSEG    (NN * RR)            // 80000
#define K1CAT   ((RR + 1) * INDIM)   // 1152
#define N2CAT   ((RR + 1) * EMBD)    // 1152

typedef __nv_bfloat16 bf16;

// GEMM pipeline constants
// NOTE: A pitch must satisfy pitch*4 ≡ 32 (mod 128) bytes for conflict-free
// LDS.64 fragment loads (APF=40 ok; APF=36 caused 2-way conflicts in R10/R11).
#define G_APF    40                   // f32 A smem pitch (floats)
#define G_APB    20                   // bf16-pair A smem pitch (u32)
#define G_BP2    264                  // B smem pitch (u32): 2*BN + 8
#define G_BSTR   (8 * G_BP2)          // B stage stride (u32) = 2112
#define STAGE_F32  (128 * G_APF * 4 + G_BSTR * 4)   // 28928
#define STAGE_BF16 (128 * G_APB * 4 + G_BSTR * 4)   // 18688
#define SMEM_F32   (4 * STAGE_F32)                   // 115712 (4-stage)
#define SMEM_BF16  (5 * STAGE_BF16)                  // 93440  (5-stage)

#define KB_BIG   ((NN + 31) / 32)     // 313 k-blocks for the big GEMM

// ---------------- scratch (device globals; no runtime allocation) ----------
__device__ bf16     g_h0b[NN * INDIM];
__device__ bf16     g_h0part[(size_t)KSPLIT * NN * INDIM];   // bf16 partials
__device__ bf16     g_S1b[(size_t)NN * K1CAT];
__device__ bf16     g_h1b[NN * HID];
__device__ bf16     g_hb2b[(size_t)NN * N2CAT];
// B operands, pair-interleaved: [blk][8 rows][2*N u32]; row r slot0 = kpair
// blk*16 + (r>>2)*8 + (r&3), slot1 = +4. Padded to full 32-k blocks.
__device__ uint32_t g_embp[(size_t)KB_BIG * 8 * (2 * INDIM)];
__device__ uint32_t g_W1p[(size_t)(K1CAT / 32) * 8 * (2 * HID)];
__device__ uint32_t g_W2p[(size_t)(HID / 32) * 8 * (2 * N2CAT)];
__device__ float    g_invdeg[NN];
__device__ int      g_cnt[NSEG];
__device__ int      g_off[NSEG + 1];
__device__ int      g_bsum[128];
__device__ int      g_cur[NSEG];
__device__ int      g_esrc[EE];
__device__ int      g_eoff[EE];

// ---------------- small helpers --------------------------------------------
__device__ __forceinline__ uint32_t packbf(float lo, float hi) {
    __nv_bfloat162 h = __float22bfloat162_rn(make_float2(lo, hi));
    return *reinterpret_cast<uint32_t*>(&h);
}
__device__ __forceinline__ float2 unpackbf(uint32_t u) {
    __nv_bfloat162 h = *reinterpret_cast<__nv_bfloat162*>(&u);
    return __bfloat1622float2(h);
}

__device__ __forceinline__ void mma_bf16(float (&c)[4], const uint32_t (&a)[4],
                                         const uint32_t (&b)[2]) {
    asm volatile(
        "mma.sync.aligned.m16n8k16.row.col.f32.bf16.bf16.f32 "
        "{%0,%1,%2,%3}, {%4,%5,%6,%7}, {%8,%9}, {%0,%1,%2,%3};"
        : "+f"(c[0]), "+f"(c[1]), "+f"(c[2]), "+f"(c[3])
        : "r"(a[0]), "r"(a[1]), "r"(a[2]), "r"(a[3]), "r"(b[0]), "r"(b[1]));
}

__device__ __forceinline__ void cp16(uint32_t dst, const void* src, bool valid) {
    int sz = valid ? 16 : 0;
    asm volatile("cp.async.cg.shared.global [%0], [%1], 16, %2;"
                 :: "r"(dst), "l"(src), "r"(sz) : "memory");
}
__device__ __forceinline__ void cp_commit() {
    asm volatile("cp.async.commit_group;" ::: "memory");
}
template <int N>
__device__ __forceinline__ void cp_waitN() {
    asm volatile("cp.async.wait_group %0;" :: "n"(N) : "memory");
}

// ---------------- CSR build --------------------------------------------------
__global__ void zeroint(int* __restrict__ p, int n) {
    int i = blockIdx.x * blockDim.x + threadIdx.x;
    if (i < n) p[i] = 0;
}

__global__ void countk(const int* __restrict__ dst, const int* __restrict__ et,
                       int* __restrict__ cnt) {
    int e = blockIdx.x * blockDim.x + threadIdx.x;
    if (e < EE) atomicAdd(&cnt[dst[e] * RR + et[e]], 1);
}

__global__ __launch_bounds__(1024)
void scan1(const int* __restrict__ cnt, int* __restrict__ off,
           int* __restrict__ bsum) {
    __shared__ int sh[1024];
    int i = blockIdx.x * 1024 + threadIdx.x;
    int v = (i < NSEG) ? cnt[i] : 0;
    sh[threadIdx.x] = v;
    __syncthreads();
#pragma unroll
    for (int d = 1; d < 1024; d <<= 1) {
        int t = (threadIdx.x >= d) ? sh[threadIdx.x - d] : 0;
        __syncthreads();
        sh[threadIdx.x] += t;
        __syncthreads();
    }
    if (i < NSEG) off[i] = sh[threadIdx.x] - v;
    if (threadIdx.x == 1023) bsum[blockIdx.x] = sh[1023];
}

__global__ __launch_bounds__(128)
void scan2(int* __restrict__ bsum, int nb) {
    __shared__ int sh[128];
    int t = threadIdx.x;
    int v = (t < nb) ? bsum[t] : 0;
    sh[t] = v;
    __syncthreads();
#pragma unroll
    for (int d = 1; d < 128; d <<= 1) {
        int u = (t >= d) ? sh[t - d] : 0;
        __syncthreads();
        sh[t] += u;
        __syncthreads();
    }
    if (t < nb) bsum[t] = sh[t] - v;
}

__global__ __launch_bounds__(1024)
void scan3(int* __restrict__ off, const int* __restrict__ bsum,
           int* __restrict__ cur) {
    int i = blockIdx.x * 1024 + threadIdx.x;
    if (i < NSEG) {
        int v = off[i] + bsum[blockIdx.x];
        off[i] = v;
        cur[i] = v;
    }
    if (i == 0) off[NSEG] = EE;
}

__global__ void placek(const int* __restrict__ src, const int* __restrict__ dst,
                       const int* __restrict__ et, int* __restrict__ cur,
                       int* __restrict__ esrc, int* __restrict__ eoff) {
    int e = blockIdx.x * blockDim.x + threadIdx.x;
    if (e >= EE) return;
    int r = et[e];
    int key = dst[e] * RR + r;
    int p = atomicAdd(&cur[key], 1);
    int s = src[e];
    esrc[p] = s;
    eoff[p] = s * N2CAT + r * EMBD;
}

__global__ void invdk(const int* __restrict__ off, float* __restrict__ inv) {
    int n = blockIdx.x * blockDim.x + threadIdx.x;
    if (n < NN) {
        int d = off[(n + 1) * RR] - off[n * RR];
        inv[n] = 1.f / (float)max(d, 1);
    }
}

// ---------------- emb -> pair-interleaved bf16 B layout ----------------------
__global__ void embconv_p(const float* __restrict__ emb, uint32_t* __restrict__ ep) {
    int idx = blockIdx.x * blockDim.x + threadIdx.x;   // KB_BIG*8*128
    if (idx >= KB_BIG * 8 * INDIM) return;
    int blk = idx >> 10;               // /(8*128)
    int rem = idx & 1023;
    int r = rem >> 7, c = rem & 127;
    int kpa = blk * 16 + (r >> 2) * 8 + (r & 3);
    int kpb = kpa + 4;
    int k0 = 2 * kpa, k1 = 2 * kpa + 1;
    float a0 = (k0 < NN) ? emb[(size_t)k0 * INDIM + c] : 0.f;
    float a1 = (k1 < NN) ? emb[(size_t)k1 * INDIM + c] : 0.f;
    int k2 = 2 * kpb, k3 = 2 * kpb + 1;
    float b0 = (k2 < NN) ? emb[(size_t)k2 * INDIM + c] : 0.f;
    float b1 = (k3 < NN) ? emb[(size_t)k3 * INDIM + c] : 0.f;
    uint2 o = make_uint2(packbf(a0, a1), packbf(b0, b1));
    *(uint2*)(ep + ((size_t)(blk * 8 + r) * (2 * INDIM) + 2 * c)) = o;
}

// ---------------- weight builders (pair-interleaved output) ------------------
__device__ __forceinline__ float wrow_val(const float* comp, const float* basis,
                                          const float* root, int k, int o,
                                          int Kin, int No) {
    if (k < RR * Kin) {
        int r = k / Kin, i = k - r * Kin;
        float s = 0.f;
#pragma unroll
        for (int b = 0; b < RR; b++)
            s += comp[r * RR + b] * basis[((size_t)b * Kin + i) * No + o];
        return s;
    }
    return root[(size_t)(k - RR * Kin) * No + o];
}

__global__ void wbuild_rows_p(const float* __restrict__ comp,
                              const float* __restrict__ basis,
                              const float* __restrict__ root,
                              uint32_t* __restrict__ Wp, int Kin, int No) {
    int nblk = ((RR + 1) * Kin) / 32;
    int idx = blockIdx.x * blockDim.x + threadIdx.x;
    if (idx >= nblk * 8 * No) return;
    int blk = idx / (8 * No);
    int rem = idx - blk * 8 * No;
    int r = rem / No, c = rem - r * No;
    int kpa = blk * 16 + (r >> 2) * 8 + (r & 3);
    int kpb = kpa + 4;
    uint2 o;
    o.x = packbf(wrow_val(comp, basis, root, 2 * kpa,     c, Kin, No),
                 wrow_val(comp, basis, root, 2 * kpa + 1, c, Kin, No));
    o.y = packbf(wrow_val(comp, basis, root, 2 * kpb,     c, Kin, No),
                 wrow_val(comp, basis, root, 2 * kpb + 1, c, Kin, No));
    *(uint2*)(Wp + ((size_t)(blk * 8 + r) * (2 * No) + 2 * c)) = o;
}

__device__ __forceinline__ float wcol_val(const float* comp, const float* basis,
                                          const float* root, int i, int col,
                                          int Kin, int No) {
    int r = col / No, o = col - r * No;
    if (r < RR) {
        float s = 0.f;
#pragma unroll
        for (int b = 0; b < RR; b++)
            s += comp[r * RR + b] * basis[((size_t)b * Kin + i) * No + o];
        return s;
    }
    return root[(size_t)i * No + o];
}

__global__ void wbuild_cols_p(const float* __restrict__ comp,
                              const float* __restrict__ basis,
                              const float* __restrict__ root,
                              uint32_t* __restrict__ Wp, int Kin, int No) {
    int ncat = (RR + 1) * No;
    int nblk = Kin / 32;
    int idx = blockIdx.x * blockDim.x + threadIdx.x;
    if (idx >= nblk * 8 * ncat) return;
    int blk = idx / (8 * ncat);
    int rem = idx - blk * 8 * ncat;
    int r = rem / ncat, c = rem - r * ncat;
    int kpa = blk * 16 + (r >> 2) * 8 + (r & 3);
    int kpb = kpa + 4;
    uint2 o;
    o.x = packbf(wcol_val(comp, basis, root, 2 * kpa,     c, Kin, No),
                 wcol_val(comp, basis, root, 2 * kpa + 1, c, Kin, No));
    o.y = packbf(wcol_val(comp, basis, root, 2 * kpb,     c, Kin, No),
                 wcol_val(comp, basis, root, 2 * kpb + 1, c, Kin, No));
    *(uint2*)(Wp + ((size_t)(blk * 8 + r) * (2 * ncat) + 2 * c)) = o;
}

// ---------------- gather 1 ---------------------------------------------------
__global__ __launch_bounds__(256)
void gather1(const bf16* __restrict__ h0, const int* __restrict__ off,
             const int* __restrict__ esrc, const float* __restrict__ invd,
             bf16* __restrict__ S1) {
    int warp = (blockIdx.x * blockDim.x + threadIdx.x) >> 5;
    int lane = threadIdx.x & 31;
    if (warp >= NSEG) return;
    int n = warp >> 3, r = warp & 7;
    int b = off[warp], e = off[warp + 1];
    float ax = 0.f, ay = 0.f, az = 0.f, aw = 0.f;
    int i = b;
    for (; i + 8 <= e; i += 8) {
        uint2 u[8];
#pragma unroll
        for (int j = 0; j < 8; j++)
            u[j] = *(const uint2*)(h0 + (size_t)esrc[i + j] * INDIM + lane * 4);
#pragma unroll
        for (int j = 0; j < 8; j++) {
            float2 p;
            p = unpackbf(u[j].x); ax += p.x; ay += p.y;
            p = unpackbf(u[j].y); az += p.x; aw += p.y;
        }
    }
    for (; i + 4 <= e; i += 4) {
        uint2 u[4];
#pragma unroll
        for (int j = 0; j < 4; j++)
            u[j] = *(const uint2*)(h0 + (size_t)esrc[i + j] * INDIM + lane * 4);
#pragma unroll
        for (int j = 0; j < 4; j++) {
            float2 p;
            p = unpackbf(u[j].x); ax += p.x; ay += p.y;
            p = unpackbf(u[j].y); az += p.x; aw += p.y;
        }
    }
    for (; i < e; i++) {
        uint2 u = *(const uint2*)(h0 + (size_t)esrc[i] * INDIM + lane * 4);
        float2 p;
        p = unpackbf(u.x); ax += p.x; ay += p.y;
        p = unpackbf(u.y); az += p.x; aw += p.y;
    }
    float w = invd[n];
    uint2 o;
    o.x = packbf(ax * w, ay * w);
    o.y = packbf(az * w, aw * w);
    *(uint2*)(S1 + (size_t)n * K1CAT + r * INDIM + lane * 4) = o;
}

// ---------------- gather 2 fused with decoder --------------------------------
__global__ __launch_bounds__(256)
void gather2_dec(const bf16* __restrict__ hb2, const int* __restrict__ off,
                 const int* __restrict__ eoff, const float* __restrict__ invd,
                 const float* __restrict__ bias, const float* __restrict__ wdec,
                 float* __restrict__ out) {
    __shared__ float swdec[EMBD * CC];   // 16 KB
    __shared__ float srow[8][EMBD];      // 4 KB
    int tid  = threadIdx.x;
    int warp = tid >> 5;
    int lane = tid & 31;
    for (int i = tid; i < EMBD * CC; i += 256) swdec[i] = wdec[i];
    __syncthreads();

    int n = blockIdx.x * 8 + warp;
    if (n >= NN) return;
    int b = off[n * RR], e = off[n * RR + RR];
    const bf16* hp = hb2 + lane * 4;
    float ax = 0.f, ay = 0.f, az = 0.f, aw = 0.f;
    int i = b;
    for (; i + 8 <= e; i += 8) {
        int o_[8];
#pragma unroll
        for (int j = 0; j < 8; j++) o_[j] = eoff[i + j];
        uint2 u[8];
#pragma unroll
        for (int j = 0; j < 8; j++) u[j] = *(const uint2*)(hp + (size_t)o_[j]);
#pragma unroll
        for (int j = 0; j < 8; j++) {
            float2 p;
            p = unpackbf(u[j].x); ax += p.x; ay += p.y;
            p = unpackbf(u[j].y); az += p.x; aw += p.y;
        }
    }
    for (; i + 4 <= e; i += 4) {
        int o_[4];
#pragma unroll
        for (int j = 0; j < 4; j++) o_[j] = eoff[i + j];
        uint2 u[4];
#pragma unroll
        for (int j = 0; j < 4; j++) u[j] = *(const uint2*)(hp + (size_t)o_[j]);
#pragma unroll
        for (int j = 0; j < 4; j++) {
            float2 p;
            p = unpackbf(u[j].x); ax += p.x; ay += p.y;
            p = unpackbf(u[j].y); az += p.x; aw += p.y;
        }
    }
    for (; i < e; i++) {
        uint2 u = *(const uint2*)(hp + (size_t)eoff[i]);
        float2 p;
        p = unpackbf(u.x); ax += p.x; ay += p.y;
        p = unpackbf(u.y); az += p.x; aw += p.y;
    }
    float w = invd[n];
    uint2 us = *(const uint2*)(hb2 + (size_t)n * N2CAT + RR * EMBD + lane * 4);
    float2 s0 = unpackbf(us.x), s1 = unpackbf(us.y);
    float4 bs = *(const float4*)(bias + lane * 4);
    float4 o;
    o.x = fmaxf(ax * w + s0.x + bs.x, 0.f);
    o.y = fmaxf(ay * w + s0.y + bs.y, 0.f);
    o.z = fmaxf(az * w + s1.x + bs.z, 0.f);
    o.w = fmaxf(aw * w + s1.y + bs.w, 0.f);
    ((float4*)srow[warp])[lane] = o;
    __syncwarp();

    float logit = 0.f;
#pragma unroll 4
    for (int k = 0; k < EMBD; k++)
        logit += srow[warp][k] * swdec[k * CC + lane];
    float mx = logit;
#pragma unroll
    for (int d = 16; d; d >>= 1) mx = fmaxf(mx, __shfl_xor_sync(~0u, mx, d));
    float ex = expf(logit - mx);
    float sm = ex;
#pragma unroll
    for (int d = 16; d; d >>= 1) sm += __shfl_xor_sync(~0u, sm, d);
    out[(size_t)n * CC + lane] = ex / sm;
}

// ---------------- cp.async multi-stage bf16 tensor-core GEMM ----------------
// B is pair-interleaved u32 [K/32 blocks][8 rows][2*N], padded to full blocks.
// Warp grid 4(M) x 2(N). Output always packed bf16 pairs; if PART, the write
// goes to partial buffer at z*M*N (split-K), else to the final C (+bias/relu).
template <int ABF, int PART, int EPI, int ST>
__global__ __launch_bounds__(256, 2)
void gemm_tc(const void* __restrict__ Av, const uint32_t* __restrict__ Bp,
             void* __restrict__ Cv, const float* __restrict__ bias,
             int M, int N, int K) {
    constexpr int BM = 128, BK = 32, KP = 16;
    constexpr int MT = 2, NT = 8;
    constexpr int ASTRIDE = ABF ? (BM * G_APB) : (BM * G_APF);   // u32/stage
    constexpr int BSTRIDE = G_BSTR;

    extern __shared__ __align__(16) char smraw[];
    float*    Asf = (float*)smraw;
    uint32_t* Asb = (uint32_t*)smraw;
    uint32_t* Bsm = (uint32_t*)(smraw + (size_t)ST * ASTRIDE * 4);
    const uint32_t sbase = (uint32_t)__cvta_generic_to_shared(smraw);
    const uint32_t sbB   = sbase + ST * ASTRIDE * 4;

    const int tid    = threadIdx.x;
    const int lane   = tid & 31;
    const int warpid = tid >> 5;
    const int warpM  = warpid >> 1;   // 0..3
    const int warpN  = warpid & 1;    // 0..1
    const int grp    = lane >> 2;
    const int quad   = lane & 3;

    const int m0 = blockIdx.x * BM;
    const int n0 = blockIdx.y * 128;

    const int kbTot = (K + BK - 1) / BK;
    const int kb0 = (int)(((long long)blockIdx.z * kbTot) / gridDim.z);
    const int kb1 = (int)(((long long)(blockIdx.z + 1) * kbTot) / gridDim.z);

    // ---- hoisted per-thread load coordinates ----
    const float* aPtrF[4]; const bf16* aPtrB[2];
    uint32_t aDst[4]; bool aVal[4]; int aKmax[4];
    if (ABF == 0) {
        const float* A = (const float*)Av;
        int acol = (tid & 7) * 4;
#pragma unroll
        for (int i = 0; i < 4; i++) {
            int r = (tid >> 3) + i * 32;
            aVal[i]  = (m0 + r) < M;
            aPtrF[i] = A + (size_t)(m0 + r) * K + acol;
            aDst[i]  = sbase + (uint32_t)(r * G_APF + acol) * 4;
            aKmax[i] = (K - 1 - acol) / BK;
        }
    } else {
        const bf16* A = (const bf16*)Av;
        int acol = (tid & 3) * 8;
#pragma unroll
        for (int i = 0; i < 2; i++) {
            int r = (tid >> 2) + i * 64;
            aVal[i]  = (m0 + r) < M;
            aPtrB[i] = A + (size_t)(m0 + r) * K + acol;
            aDst[i]  = sbase + (uint32_t)(r * G_APB + (acol >> 1)) * 4;
        }
    }
    const uint32_t* bPtr[2]; uint32_t bDst[2];
    {
#pragma unroll
        for (int i = 0; i < 2; i++) {
            int id = tid + i * 256;
            int pr = id >> 6, cg = id & 63;
            bPtr[i] = Bp + (size_t)pr * (2 * N) + 2 * n0 + cg * 4;
            bDst[i] = sbB + (uint32_t)(pr * G_BP2 + cg * 4) * 4;
        }
    }
    const size_t bRowStride = (size_t)8 * (2 * N);

    auto issue = [&](int kb, int s) {
        if (ABF == 0) {
#pragma unroll
            for (int i = 0; i < 4; i++) {
                bool v = aVal[i] && (kb <= aKmax[i]);
                const void* src = v ? (const void*)(aPtrF[i] + (size_t)kb * BK)
                                    : (const void*)Av;
                cp16(aDst[i] + s * (ASTRIDE * 4), src, v);
            }
        } else {
#pragma unroll
            for (int i = 0; i < 2; i++) {
                bool v = aVal[i];
                const void* src = v ? (const void*)(aPtrB[i] + (size_t)kb * BK)
                                    : (const void*)Av;
                cp16(aDst[i] + s * (ASTRIDE * 4), src, v);
            }
        }
#pragma unroll
        for (int i = 0; i < 2; i++)
            cp16(bDst[i] + s * (BSTRIDE * 4), bPtr[i] + (size_t)kb * bRowStride,
                 true);
    };

    float acc[MT][NT][4];
#pragma unroll
    for (int mi = 0; mi < MT; mi++)
#pragma unroll
        for (int ni = 0; ni < NT; ni++)
#pragma unroll
            for (int j = 0; j < 4; j++) acc[mi][ni][j] = 0.f;

    const int nkb = kb1 - kb0;
#pragma unroll
    for (int s = 0; s < ST - 1; s++) {
        if (s < nkb) issue(kb0 + s, s);
        cp_commit();
    }

    int cur = 0;
    for (int kb = kb0; kb < kb1; ++kb) {
        cp_waitN<ST - 2>();
        __syncthreads();

#pragma unroll
        for (int kk2 = 0; kk2 < KP; kk2 += 8) {
            uint32_t a[MT][4];
            uint32_t b[NT][2];
#pragma unroll
            for (int mi = 0; mi < MT; mi++) {
                int r0 = warpM * 32 + mi * 16 + grp;
                if (ABF == 0) {
                    const float* base = Asf + cur * ASTRIDE;
                    float2 f0 = *(const float2*)(base + r0 * G_APF + 2 * (kk2 + quad));
                    float2 f1 = *(const float2*)(base + (r0 + 8) * G_APF + 2 * (kk2 + quad));
                    float2 f2 = *(const float2*)(base + r0 * G_APF + 2 * (kk2 + quad + 4));
                    float2 f3 = *(const float2*)(base + (r0 + 8) * G_APF + 2 * (kk2 + quad + 4));
                    a[mi][0] = packbf(f0.x, f0.y);
                    a[mi][1] = packbf(f1.x, f1.y);
                    a[mi][2] = packbf(f2.x, f2.y);
                    a[mi][3] = packbf(f3.x, f3.y);
                } else {
                    const uint32_t* base = Asb + cur * ASTRIDE;
                    a[mi][0] = base[r0 * G_APB + kk2 + quad];
                    a[mi][1] = base[(r0 + 8) * G_APB + kk2 + quad];
                    a[mi][2] = base[r0 * G_APB + kk2 + quad + 4];
                    a[mi][3] = base[(r0 + 8) * G_APB + kk2 + quad + 4];
                }
            }
            const uint32_t* bb = Bsm + cur * BSTRIDE
                               + ((kk2 >> 1) + quad) * G_BP2;
#pragma unroll
            for (int ni = 0; ni < NT; ni++) {
                int c = warpN * 64 + ni * 8 + grp;
                uint2 bv = *(const uint2*)(bb + 2 * c);
                b[ni][0] = bv.x;
                b[ni][1] = bv.y;
            }
#pragma unroll
            for (int mi = 0; mi < MT; mi++)
#pragma unroll
                for (int ni = 0; ni < NT; ni++)
                    mma_bf16(acc[mi][ni], a[mi], b[ni]);
        }

        int nxt = kb + (ST - 1);
        if (nxt < kb1) issue(nxt, (cur + ST - 1) % ST);
        cp_commit();
        cur = (cur + 1 == ST) ? 0 : cur + 1;
    }

    bf16* Cp = (bf16*)Cv;
    if (PART) Cp += (size_t)blockIdx.z * M * N;
#pragma unroll
    for (int mi = 0; mi < MT; mi++) {
        int r0 = m0 + warpM * 32 + mi * 16 + grp;
#pragma unroll
        for (int ni = 0; ni < NT; ni++) {
            int c = n0 + warpN * 64 + ni * 8 + quad * 2;
            float b0 = 0.f, b1 = 0.f;
            if (EPI) { b0 = bias[c]; b1 = bias[c + 1]; }
#pragma unroll
            for (int h = 0; h < 2; h++) {
                int r = r0 + h * 8;
                if (r >= M) continue;
                float v0 = acc[mi][ni][2 * h + 0];
                float v1 = acc[mi][ni][2 * h + 1];
                if (EPI) {
                    v0 = fmaxf(v0 + b0, 0.f);
                    v1 = fmaxf(v1 + b1, 0.f);
                }
                *(uint32_t*)(Cp + (size_t)r * N + c) = packbf(v0, v1);
            }
        }
    }
}

// combine KSPLIT bf16 partials, relu, write bf16 h0 AND the S1 tail block
__global__ void combine_relu(bf16* __restrict__ h0, bf16* __restrict__ S1,
                             const bf16* __restrict__ part) {
    int i = blockIdx.x * blockDim.x + threadIdx.x;   // over bf16 pairs
    if (i >= NN * INDIM / 2) return;
    const uint32_t* pp = (const uint32_t*)part;
    float a = 0.f, b = 0.f;
#pragma unroll
    for (int z = 0; z < KSPLIT; z++) {
        float2 s = unpackbf(pp[(size_t)z * (NN * INDIM / 2) + i]);
        a += s.x;
        b += s.y;
    }
    a = fmaxf(a, 0.f);
    b = fmaxf(b, 0.f);
    uint32_t pk = packbf(a, b);
    *(uint32_t*)(h0 + 2 * (size_t)i) = pk;
    int n = (2 * i) >> 7;
    int col = (2 * i) & 127;
    *(uint32_t*)(S1 + (size_t)n * K1CAT + RR * INDIM + col) = pk;
}

// ---------------- launch ----------------------------------------------------
extern "C" void kernel_launch(void* const* d_in, const int* in_sizes, int n_in,
                              void* d_out, int out_size) {
    const float* x      = (const float*)d_in[0];
    const int*   eidx   = (const int*)  d_in[1];
    const int*   etype  = (const int*)  d_in[2];
    const float* emb    = (const float*)d_in[3];
    const float* comp1  = (const float*)d_in[4];
    const float* basis1 = (const float*)d_in[5];
    const float* root1  = (const float*)d_in[6];
    const float* bias1  = (const float*)d_in[7];
    const float* comp2  = (const float*)d_in[8];
    const float* basis2 = (const float*)d_in[9];
    const float* root2  = (const float*)d_in[10];
    const float* bias2  = (const float*)d_in[11];
    const float* wdec   = (const float*)d_in[12];
    float* out = (float*)d_out;

    const int* srcp = eidx;
    const int* dstp = eidx + EE;

    bf16 *h0b, *h0p, *S1b, *h1b, *hb2b;
    float *invd;
    uint32_t *embp, *W1p, *W2p;
    int *cnt, *off, *bsum, *cur, *esrc, *eoff;
    cudaGetSymbolAddress((void**)&h0b,  g_h0b);
    cudaGetSymbolAddress((void**)&h0p,  g_h0part);
    cudaGetSymbolAddress((void**)&S1b,  g_S1b);
    cudaGetSymbolAddress((void**)&h1b,  g_h1b);
    cudaGetSymbolAddress((void**)&hb2b, g_hb2b);
    cudaGetSymbolAddress((void**)&embp, g_embp);
    cudaGetSymbolAddress((void**)&W1p,  g_W1p);
    cudaGetSymbolAddress((void**)&W2p,  g_W2p);
    cudaGetSymbolAddress((void**)&invd, g_invdeg);
    cudaGetSymbolAddress((void**)&cnt,  g_cnt);
    cudaGetSymbolAddress((void**)&off,  g_off);
    cudaGetSymbolAddress((void**)&bsum, g_bsum);
    cudaGetSymbolAddress((void**)&cur,  g_cur);
    cudaGetSymbolAddress((void**)&esrc, g_esrc);
    cudaGetSymbolAddress((void**)&eoff, g_eoff);

    cudaFuncSetAttribute(gemm_tc<0, 1, 0, 4>,
                         cudaFuncAttributeMaxDynamicSharedMemorySize, SMEM_F32);
    cudaFuncSetAttribute(gemm_tc<1, 0, 1, 5>,
                         cudaFuncAttributeMaxDynamicSharedMemorySize, SMEM_BF16);
    cudaFuncSetAttribute(gemm_tc<1, 0, 0, 5>,
                         cudaFuncAttributeMaxDynamicSharedMemorySize, SMEM_BF16);

    cudaStream_t s2;
    cudaEvent_t evF, evJ;
    cudaStreamCreateWithFlags(&s2, cudaStreamNonBlocking);
    cudaEventCreateWithFlags(&evF, cudaEventDisableTiming);
    cudaEventCreateWithFlags(&evJ, cudaEventDisableTiming);

    const int SCAN_BLKS = (NSEG + 1023) / 1024;   // 79

    // submission #1: emb pre-pack (main)
    embconv_p<<<(KB_BIG * 8 * INDIM + 255) / 256, 256>>>(emb, embp);

    cudaEventRecord(evF, 0);
    cudaStreamWaitEvent(s2, evF, 0);

    // submissions #2-3 on side stream
    zeroint<<<(NSEG + 255) / 256, 256, 0, s2>>>(cnt, NSEG);
    countk<<<(EE + 255) / 256, 256, 0, s2>>>(dstp, etype, cnt);

    // submission #4: big GEMM (ncu capture target), 4-stage, bf16 partials
    gemm_tc<0, 1, 0, 4><<<dim3((NN + 127) / 128, 1, KSPLIT), 256, SMEM_F32>>>(
        x, embp, h0p, nullptr, NN, INDIM, NN);

    // rest of side stream
    scan1<<<SCAN_BLKS, 1024, 0, s2>>>(cnt, off, bsum);
    scan2<<<1, 128, 0, s2>>>(bsum, SCAN_BLKS);
    scan3<<<SCAN_BLKS, 1024, 0, s2>>>(off, bsum, cur);
    placek<<<(EE + 255) / 256, 256, 0, s2>>>(srcp, dstp, etype, cur, esrc, eoff);
    invdk<<<(NN + 255) / 256, 256, 0, s2>>>(off, invd);
    wbuild_rows_p<<<((K1CAT / 32) * 8 * HID + 255) / 256, 256, 0, s2>>>(
        comp1, basis1, root1, W1p, INDIM, HID);
    wbuild_cols_p<<<((HID / 32) * 8 * N2CAT + 255) / 256, 256, 0, s2>>>(
        comp2, basis2, root2, W2p, HID, EMBD);
    cudaEventRecord(evJ, s2);

    // main stream continues
    combine_relu<<<(NN * INDIM / 2 + 255) / 256, 256>>>(h0b, S1b, h0p);

    cudaStreamWaitEvent(0, evJ, 0);

    // layer 1
    gather1<<<(NSEG * 32 + 255) / 256, 256>>>(h0b, off, esrc, invd, S1b);
    gemm_tc<1, 0, 1, 5><<<dim3((NN + 127) / 128, HID / 128, 1), 256, SMEM_BF16>>>(
        S1b, W1p, h1b, bias1, NN, HID, K1CAT);

    // layer 2 (transform-first)
    gemm_tc<1, 0, 0, 5><<<dim3((NN + 127) / 128, N2CAT / 128, 1), 256, SMEM_BF16>>>(
        h1b, W2p, hb2b, nullptr, NN, N2CAT, HID);

    // gather 2 + decoder fused
    gather2_dec<<<NN / 8, 256>>>(hb2b, off, eoff, invd, bias2, wdec, out);
}

// round 15
// speedup vs baseline: 1.4441x; 1.4441x over previous
#include <cuda_runtime.h>
#include <cuda_bf16.h>
#include <cstdint>
#include <cstddef>

#define NN      10000
#define INDIM   128
#define HID     256
#define EMBD    128
#define RR      8
#define CC      32
#define EE      640000
#define KSPLIT  11
#define NSEG    (NN * RR)            // 80000
#define K1CAT   ((RR + 1) * INDIM)   // 1152
#define N2CAT   ((RR + 1) * EMBD)    // 1152

typedef __nv_bfloat16 bf16;

// GEMM pipeline constants
// NOTE: A pitch must satisfy pitch*4 ≡ 32 (mod 128) bytes for conflict-free
// LDS.64 fragment loads (APF=40 ok; APF=36 caused 2-way conflicts in R10/R11).
// NOTE: split-K partials must stay f32 with >=8B coalesced stores (bf16
// 4B half-sector partial stores cost +53us in R14).
#define G_APF    40                   // f32 A smem pitch (floats)
#define G_APB    20                   // bf16-pair A smem pitch (u32)
#define KB_BIG   ((NN + 31) / 32)     // 313 k-blocks for the big GEMM

#define BP2(BN)    (2 * (BN) + 8)                     // B smem pitch (u32)
#define BSTR(BN)   (8 * BP2(BN))                      // B stage stride (u32)
#define STG_F32(BN)  (128 * G_APF * 4 + BSTR(BN) * 4)
#define STG_B16(BN)  (128 * G_APB * 4 + BSTR(BN) * 4)
#define SMEM_F32     (4 * STG_F32(128))               // 115712 (4-stage)
#define SMEM_B16_128 (5 * STG_B16(128))               // 93440  (5-stage)
#define SMEM_B16_64  (5 * STG_B16(64))                // 72960  (5-stage)

// ---------------- scratch (device globals; no runtime allocation) ----------
__device__ bf16     g_h0b[NN * INDIM];
__device__ float    g_h0part[(size_t)KSPLIT * NN * INDIM];
__device__ bf16     g_S1b[(size_t)NN * K1CAT];
__device__ bf16     g_h1b[NN * HID];
__device__ bf16     g_hb2b[(size_t)NN * N2CAT];
// B operands, pair-interleaved: [blk][8 rows][2*N u32]; row r slot0 = kpair
// blk*16 + (r>>2)*8 + (r&3), slot1 = +4. Padded to full 32-k blocks.
__device__ uint32_t g_embp[(size_t)KB_BIG * 8 * (2 * INDIM)];
__device__ uint32_t g_W1p[(size_t)(K1CAT / 32) * 8 * (2 * HID)];
__device__ uint32_t g_W2p[(size_t)(HID / 32) * 8 * (2 * N2CAT)];
__device__ float    g_invdeg[NN];
__device__ int      g_cnt[NSEG];
__device__ int      g_off[NSEG + 1];
__device__ int      g_bsum[128];
__device__ int      g_cur[NSEG];
__device__ int      g_esrc[EE];
__device__ int      g_eoff[EE];

// ---------------- small helpers --------------------------------------------
__device__ __forceinline__ uint32_t packbf(float lo, float hi) {
    __nv_bfloat162 h = __float22bfloat162_rn(make_float2(lo, hi));
    return *reinterpret_cast<uint32_t*>(&h);
}
__device__ __forceinline__ float2 unpackbf(uint32_t u) {
    __nv_bfloat162 h = *reinterpret_cast<__nv_bfloat162*>(&u);
    return __bfloat1622float2(h);
}

__device__ __forceinline__ void mma_bf16(float (&c)[4], const uint32_t (&a)[4],
                                         const uint32_t (&b)[2]) {
    asm volatile(
        "mma.sync.aligned.m16n8k16.row.col.f32.bf16.bf16.f32 "
        "{%0,%1,%2,%3}, {%4,%5,%6,%7}, {%8,%9}, {%0,%1,%2,%3};"
        : "+f"(c[0]), "+f"(c[1]), "+f"(c[2]), "+f"(c[3])
        : "r"(a[0]), "r"(a[1]), "r"(a[2]), "r"(a[3]), "r"(b[0]), "r"(b[1]));
}

__device__ __forceinline__ void cp16(uint32_t dst, const void* src, bool valid) {
    int sz = valid ? 16 : 0;
    asm volatile("cp.async.cg.shared.global [%0], [%1], 16, %2;"
                 :: "r"(dst), "l"(src), "r"(sz) : "memory");
}
__device__ __forceinline__ void cp_commit() {
    asm volatile("cp.async.commit_group;" ::: "memory");
}
template <int N>
__device__ __forceinline__ void cp_waitN() {
    asm volatile("cp.async.wait_group %0;" :: "n"(N) : "memory");
}

// ---------------- CSR build --------------------------------------------------
__global__ void zeroint(int* __restrict__ p, int n) {
    int i = blockIdx.x * blockDim.x + threadIdx.x;
    if (i < n) p[i] = 0;
}

__global__ void countk(const int* __restrict__ dst, const int* __restrict__ et,
                       int* __restrict__ cnt) {
    int e = blockIdx.x * blockDim.x + threadIdx.x;
    if (e < EE) atomicAdd(&cnt[dst[e] * RR + et[e]], 1);
}

__global__ __launch_bounds__(1024)
void scan1(const int* __restrict__ cnt, int* __restrict__ off,
           int* __restrict__ bsum) {
    __shared__ int sh[1024];
    int i = blockIdx.x * 1024 + threadIdx.x;
    int v = (i < NSEG) ? cnt[i] : 0;
    sh[threadIdx.x] = v;
    __syncthreads();
#pragma unroll
    for (int d = 1; d < 1024; d <<= 1) {
        int t = (threadIdx.x >= d) ? sh[threadIdx.x - d] : 0;
        __syncthreads();
        sh[threadIdx.x] += t;
        __syncthreads();
    }
    if (i < NSEG) off[i] = sh[threadIdx.x] - v;
    if (threadIdx.x == 1023) bsum[blockIdx.x] = sh[1023];
}

__global__ __launch_bounds__(128)
void scan2(int* __restrict__ bsum, int nb) {
    __shared__ int sh[128];
    int t = threadIdx.x;
    int v = (t < nb) ? bsum[t] : 0;
    sh[t] = v;
    __syncthreads();
#pragma unroll
    for (int d = 1; d < 128; d <<= 1) {
        int u = (t >= d) ? sh[t - d] : 0;
        __syncthreads();
        sh[t] += u;
        __syncthreads();
    }
    if (t < nb) bsum[t] = sh[t] - v;
}

__global__ __launch_bounds__(1024)
void scan3(int* __restrict__ off, const int* __restrict__ bsum,
           int* __restrict__ cur) {
    int i = blockIdx.x * 1024 + threadIdx.x;
    if (i < NSEG) {
        int v = off[i] + bsum[blockIdx.x];
        off[i] = v;
        cur[i] = v;
    }
    if (i == 0) off[NSEG] = EE;
}

__global__ void placek(const int* __restrict__ src, const int* __restrict__ dst,
                       const int* __restrict__ et, int* __restrict__ cur,
                       int* __restrict__ esrc, int* __restrict__ eoff) {
    int e = blockIdx.x * blockDim.x + threadIdx.x;
    if (e >= EE) return;
    int r = et[e];
    int key = dst[e] * RR + r;
    int p = atomicAdd(&cur[key], 1);
    int s = src[e];
    esrc[p] = s;
    eoff[p] = s * N2CAT + r * EMBD;
}

__global__ void invdk(const int* __restrict__ off, float* __restrict__ inv) {
    int n = blockIdx.x * blockDim.x + threadIdx.x;
    if (n < NN) {
        int d = off[(n + 1) * RR] - off[n * RR];
        inv[n] = 1.f / (float)max(d, 1);
    }
}

// ---------------- emb -> pair-interleaved bf16 B layout ----------------------
__global__ void embconv_p(const float* __restrict__ emb, uint32_t* __restrict__ ep) {
    int idx = blockIdx.x * blockDim.x + threadIdx.x;   // KB_BIG*8*128
    if (idx >= KB_BIG * 8 * INDIM) return;
    int blk = idx >> 10;               // /(8*128)
    int rem = idx & 1023;
    int r = rem >> 7, c = rem & 127;
    int kpa = blk * 16 + (r >> 2) * 8 + (r & 3);
    int kpb = kpa + 4;
    int k0 = 2 * kpa, k1 = 2 * kpa + 1;
    float a0 = (k0 < NN) ? emb[(size_t)k0 * INDIM + c] : 0.f;
    float a1 = (k1 < NN) ? emb[(size_t)k1 * INDIM + c] : 0.f;
    int k2 = 2 * kpb, k3 = 2 * kpb + 1;
    float b0 = (k2 < NN) ? emb[(size_t)k2 * INDIM + c] : 0.f;
    float b1 = (k3 < NN) ? emb[(size_t)k3 * INDIM + c] : 0.f;
    uint2 o = make_uint2(packbf(a0, a1), packbf(b0, b1));
    *(uint2*)(ep + ((size_t)(blk * 8 + r) * (2 * INDIM) + 2 * c)) = o;
}

// ---------------- weight builders (pair-interleaved output) ------------------
__device__ __forceinline__ float wrow_val(const float* comp, const float* basis,
                                          const float* root, int k, int o,
                                          int Kin, int No) {
    if (k < RR * Kin) {
        int r = k / Kin, i = k - r * Kin;
        float s = 0.f;
#pragma unroll
        for (int b = 0; b < RR; b++)
            s += comp[r * RR + b] * basis[((size_t)b * Kin + i) * No + o];
        return s;
    }
    return root[(size_t)(k - RR * Kin) * No + o];
}

__global__ void wbuild_rows_p(const float* __restrict__ comp,
                              const float* __restrict__ basis,
                              const float* __restrict__ root,
                              uint32_t* __restrict__ Wp, int Kin, int No) {
    int nblk = ((RR + 1) * Kin) / 32;
    int idx = blockIdx.x * blockDim.x + threadIdx.x;
    if (idx >= nblk * 8 * No) return;
    int blk = idx / (8 * No);
    int rem = idx - blk * 8 * No;
    int r = rem / No, c = rem - r * No;
    int kpa = blk * 16 + (r >> 2) * 8 + (r & 3);
    int kpb = kpa + 4;
    uint2 o;
    o.x = packbf(wrow_val(comp, basis, root, 2 * kpa,     c, Kin, No),
                 wrow_val(comp, basis, root, 2 * kpa + 1, c, Kin, No));
    o.y = packbf(wrow_val(comp, basis, root, 2 * kpb,     c, Kin, No),
                 wrow_val(comp, basis, root, 2 * kpb + 1, c, Kin, No));
    *(uint2*)(Wp + ((size_t)(blk * 8 + r) * (2 * No) + 2 * c)) = o;
}

__device__ __forceinline__ float wcol_val(const float* comp, const float* basis,
                                          const float* root, int i, int col,
                                          int Kin, int No) {
    int r = col / No, o = col - r * No;
    if (r < RR) {
        float s = 0.f;
#pragma unroll
        for (int b = 0; b < RR; b++)
            s += comp[r * RR + b] * basis[((size_t)b * Kin + i) * No + o];
        return s;
    }
    return root[(size_t)i * No + o];
}

__global__ void wbuild_cols_p(const float* __restrict__ comp,
                              const float* __restrict__ basis,
                              const float* __restrict__ root,
                              uint32_t* __restrict__ Wp, int Kin, int No) {
    int ncat = (RR + 1) * No;
    int nblk = Kin / 32;
    int idx = blockIdx.x * blockDim.x + threadIdx.x;
    if (idx >= nblk * 8 * ncat) return;
    int blk = idx / (8 * ncat);
    int rem = idx - blk * 8 * ncat;
    int r = rem / ncat, c = rem - r * ncat;
    int kpa = blk * 16 + (r >> 2) * 8 + (r & 3);
    int kpb = kpa + 4;
    uint2 o;
    o.x = packbf(wcol_val(comp, basis, root, 2 * kpa,     c, Kin, No),
                 wcol_val(comp, basis, root, 2 * kpa + 1, c, Kin, No));
    o.y = packbf(wcol_val(comp, basis, root, 2 * kpb,     c, Kin, No),
                 wcol_val(comp, basis, root, 2 * kpb + 1, c, Kin, No));
    *(uint2*)(Wp + ((size_t)(blk * 8 + r) * (2 * ncat) + 2 * c)) = o;
}

// ---------------- gather 1 ---------------------------------------------------
__global__ __launch_bounds__(256)
void gather1(const bf16* __restrict__ h0, const int* __restrict__ off,
             const int* __restrict__ esrc, const float* __restrict__ invd,
             bf16* __restrict__ S1) {
    int warp = (blockIdx.x * blockDim.x + threadIdx.x) >> 5;
    int lane = threadIdx.x & 31;
    if (warp >= NSEG) return;
    int n = warp >> 3, r = warp & 7;
    int b = off[warp], e = off[warp + 1];
    float ax = 0.f, ay = 0.f, az = 0.f, aw = 0.f;
    int i = b;
    for (; i + 8 <= e; i += 8) {
        uint2 u[8];
#pragma unroll
        for (int j = 0; j < 8; j++)
            u[j] = *(const uint2*)(h0 + (size_t)esrc[i + j] * INDIM + lane * 4);
#pragma unroll
        for (int j = 0; j < 8; j++) {
            float2 p;
            p = unpackbf(u[j].x); ax += p.x; ay += p.y;
            p = unpackbf(u[j].y); az += p.x; aw += p.y;
        }
    }
    for (; i + 4 <= e; i += 4) {
        uint2 u[4];
#pragma unroll
        for (int j = 0; j < 4; j++)
            u[j] = *(const uint2*)(h0 + (size_t)esrc[i + j] * INDIM + lane * 4);
#pragma unroll
        for (int j = 0; j < 4; j++) {
            float2 p;
            p = unpackbf(u[j].x); ax += p.x; ay += p.y;
            p = unpackbf(u[j].y); az += p.x; aw += p.y;
        }
    }
    for (; i < e; i++) {
        uint2 u = *(const uint2*)(h0 + (size_t)esrc[i] * INDIM + lane * 4);
        float2 p;
        p = unpackbf(u.x); ax += p.x; ay += p.y;
        p = unpackbf(u.y); az += p.x; aw += p.y;
    }
    float w = invd[n];
    uint2 o;
    o.x = packbf(ax * w, ay * w);
    o.y = packbf(az * w, aw * w);
    *(uint2*)(S1 + (size_t)n * K1CAT + r * INDIM + lane * 4) = o;
}

// ---------------- gather 2 fused with decoder --------------------------------
__global__ __launch_bounds__(256)
void gather2_dec(const bf16* __restrict__ hb2, const int* __restrict__ off,
                 const int* __restrict__ eoff, const float* __restrict__ invd,
                 const float* __restrict__ bias, const float* __restrict__ wdec,
                 float* __restrict__ out) {
    __shared__ float swdec[EMBD * CC];   // 16 KB
    __shared__ float srow[8][EMBD];      // 4 KB
    int tid  = threadIdx.x;
    int warp = tid >> 5;
    int lane = tid & 31;
    for (int i = tid; i < EMBD * CC; i += 256) swdec[i] = wdec[i];
    __syncthreads();

    int n = blockIdx.x * 8 + warp;
    if (n >= NN) return;
    int b = off[n * RR], e = off[n * RR + RR];
    const bf16* hp = hb2 + lane * 4;
    float ax = 0.f, ay = 0.f, az = 0.f, aw = 0.f;
    int i = b;
    for (; i + 8 <= e; i += 8) {
        int o_[8];
#pragma unroll
        for (int j = 0; j < 8; j++) o_[j] = eoff[i + j];
        uint2 u[8];
#pragma unroll
        for (int j = 0; j < 8; j++) u[j] = *(const uint2*)(hp + (size_t)o_[j]);
#pragma unroll
        for (int j = 0; j < 8; j++) {
            float2 p;
            p = unpackbf(u[j].x); ax += p.x; ay += p.y;
            p = unpackbf(u[j].y); az += p.x; aw += p.y;
        }
    }
    for (; i + 4 <= e; i += 4) {
        int o_[4];
#pragma unroll
        for (int j = 0; j < 4; j++) o_[j] = eoff[i + j];
        uint2 u[4];
#pragma unroll
        for (int j = 0; j < 4; j++) u[j] = *(const uint2*)(hp + (size_t)o_[j]);
#pragma unroll
        for (int j = 0; j < 4; j++) {
            float2 p;
            p = unpackbf(u[j].x); ax += p.x; ay += p.y;
            p = unpackbf(u[j].y); az += p.x; aw += p.y;
        }
    }
    for (; i < e; i++) {
        uint2 u = *(const uint2*)(hp + (size_t)eoff[i]);
        float2 p;
        p = unpackbf(u.x); ax += p.x; ay += p.y;
        p = unpackbf(u.y); az += p.x; aw += p.y;
    }
    float w = invd[n];
    uint2 us = *(const uint2*)(hb2 + (size_t)n * N2CAT + RR * EMBD + lane * 4);
    float2 s0 = unpackbf(us.x), s1 = unpackbf(us.y);
    float4 bs = *(const float4*)(bias + lane * 4);
    float4 o;
    o.x = fmaxf(ax * w + s0.x + bs.x, 0.f);
    o.y = fmaxf(ay * w + s0.y + bs.y, 0.f);
    o.z = fmaxf(az * w + s1.x + bs.z, 0.f);
    o.w = fmaxf(aw * w + s1.y + bs.w, 0.f);
    ((float4*)srow[warp])[lane] = o;
    __syncwarp();

    float logit = 0.f;
#pragma unroll 4
    for (int k = 0; k < EMBD; k++)
        logit += srow[warp][k] * swdec[k * CC + lane];
    float mx = logit;
#pragma unroll
    for (int d = 16; d; d >>= 1) mx = fmaxf(mx, __shfl_xor_sync(~0u, mx, d));
    float ex = expf(logit - mx);
    float sm = ex;
#pragma unroll
    for (int d = 16; d; d >>= 1) sm += __shfl_xor_sync(~0u, sm, d);
    out[(size_t)n * CC + lane] = ex / sm;
}

// ---------------- cp.async multi-stage bf16 tensor-core GEMM ----------------
// B is pair-interleaved u32 [K/32 blocks][8 rows][2*N], padded to full blocks.
// Warp grid 4(M) x 2(N); BN templated (128 or 64).
template <int ABF, int OUTBF, int EPI, int ST, int BN>
__global__ __launch_bounds__(256, 2)
void gemm_tc(const void* __restrict__ Av, const uint32_t* __restrict__ Bp,
             void* __restrict__ Cv, const float* __restrict__ bias,
             int M, int N, int K) {
    constexpr int BM = 128, BK = 32, KP = 16;
    constexpr int MT = 2, NT = BN / 16;
    constexpr int WNC = BN / 2;                         // cols per warpN
    constexpr int BPITCH = 2 * BN + 8;                  // u32
    constexpr int ASTRIDE = ABF ? (BM * G_APB) : (BM * G_APF);
    constexpr int BSTRIDE = 8 * BPITCH;
    constexpr int LB = BN / 64;                         // B cp16 per thread

    extern __shared__ __align__(16) char smraw[];
    float*    Asf = (float*)smraw;
    uint32_t* Asb = (uint32_t*)smraw;
    uint32_t* Bsm = (uint32_t*)(smraw + (size_t)ST * ASTRIDE * 4);
    const uint32_t sbase = (uint32_t)__cvta_generic_to_shared(smraw);
    const uint32_t sbB   = sbase + ST * ASTRIDE * 4;

    const int tid    = threadIdx.x;
    const int lane   = tid & 31;
    const int warpid = tid >> 5;
    const int warpM  = warpid >> 1;   // 0..3
    const int warpN  = warpid & 1;    // 0..1
    const int grp    = lane >> 2;
    const int quad   = lane & 3;

    const int m0 = blockIdx.x * BM;
    const int n0 = blockIdx.y * BN;

    const int kbTot = (K + BK - 1) / BK;
    const int kb0 = (int)(((long long)blockIdx.z * kbTot) / gridDim.z);
    const int kb1 = (int)(((long long)(blockIdx.z + 1) * kbTot) / gridDim.z);

    // ---- hoisted per-thread load coordinates ----
    const float* aPtrF[4]; const bf16* aPtrB[2];
    uint32_t aDst[4]; bool aVal[4]; int aKmax[4];
    if (ABF == 0) {
        const float* A = (const float*)Av;
        int acol = (tid & 7) * 4;
#pragma unroll
        for (int i = 0; i < 4; i++) {
            int r = (tid >> 3) + i * 32;
            aVal[i]  = (m0 + r) < M;
            aPtrF[i] = A + (size_t)(m0 + r) * K + acol;
            aDst[i]  = sbase + (uint32_t)(r * G_APF + acol) * 4;
            aKmax[i] = (K - 1 - acol) / BK;
        }
    } else {
        const bf16* A = (const bf16*)Av;
        int acol = (tid & 3) * 8;
#pragma unroll
        for (int i = 0; i < 2; i++) {
            int r = (tid >> 2) + i * 64;
            aVal[i]  = (m0 + r) < M;
            aPtrB[i] = A + (size_t)(m0 + r) * K + acol;
            aDst[i]  = sbase + (uint32_t)(r * G_APB + (acol >> 1)) * 4;
        }
    }
    const uint32_t* bPtr[LB]; uint32_t bDst[LB];
    {
#pragma unroll
        for (int i = 0; i < LB; i++) {
            int id = tid + i * 256;
            int pr = id / WNC, cg = id % WNC;           // WNC u32-groups/row
            bPtr[i] = Bp + (size_t)pr * (2 * N) + 2 * n0 + cg * 4;
            bDst[i] = sbB + (uint32_t)(pr * BPITCH + cg * 4) * 4;
        }
    }
    const size_t bRowStride = (size_t)8 * (2 * N);

    auto issue = [&](int kb, int s) {
        if (ABF == 0) {
#pragma unroll
            for (int i = 0; i < 4; i++) {
                bool v = aVal[i] && (kb <= aKmax[i]);
                const void* src = v ? (const void*)(aPtrF[i] + (size_t)kb * BK)
                                    : (const void*)Av;
                cp16(aDst[i] + s * (ASTRIDE * 4), src, v);
            }
        } else {
#pragma unroll
            for (int i = 0; i < 2; i++) {
                bool v = aVal[i];
                const void* src = v ? (const void*)(aPtrB[i] + (size_t)kb * BK)
                                    : (const void*)Av;
                cp16(aDst[i] + s * (ASTRIDE * 4), src, v);
            }
        }
#pragma unroll
        for (int i = 0; i < LB; i++)
            cp16(bDst[i] + s * (BSTRIDE * 4), bPtr[i] + (size_t)kb * bRowStride,
                 true);
    };

    float acc[MT][NT][4];
#pragma unroll
    for (int mi = 0; mi < MT; mi++)
#pragma unroll
        for (int ni = 0; ni < NT; ni++)
#pragma unroll
            for (int j = 0; j < 4; j++) acc[mi][ni][j] = 0.f;

    const int nkb = kb1 - kb0;
#pragma unroll
    for (int s = 0; s < ST - 1; s++) {
        if (s < nkb) issue(kb0 + s, s);
        cp_commit();
    }

    int cur = 0;
    for (int kb = kb0; kb < kb1; ++kb) {
        cp_waitN<ST - 2>();
        __syncthreads();

#pragma unroll
        for (int kk2 = 0; kk2 < KP; kk2 += 8) {
            uint32_t a[MT][4];
            uint32_t b[NT][2];
#pragma unroll
            for (int mi = 0; mi < MT; mi++) {
                int r0 = warpM * 32 + mi * 16 + grp;
                if (ABF == 0) {
                    const float* base = Asf + cur * ASTRIDE;
                    float2 f0 = *(const float2*)(base + r0 * G_APF + 2 * (kk2 + quad));
                    float2 f1 = *(const float2*)(base + (r0 + 8) * G_APF + 2 * (kk2 + quad));
                    float2 f2 = *(const float2*)(base + r0 * G_APF + 2 * (kk2 + quad + 4));
                    float2 f3 = *(const float2*)(base + (r0 + 8) * G_APF + 2 * (kk2 + quad + 4));
                    a[mi][0] = packbf(f0.x, f0.y);
                    a[mi][1] = packbf(f1.x, f1.y);
                    a[mi][2] = packbf(f2.x, f2.y);
                    a[mi][3] = packbf(f3.x, f3.y);
                } else {
                    const uint32_t* base = Asb + cur * ASTRIDE;
                    a[mi][0] = base[r0 * G_APB + kk2 + quad];
                    a[mi][1] = base[(r0 + 8) * G_APB + kk2 + quad];
                    a[mi][2] = base[r0 * G_APB + kk2 + quad + 4];
                    a[mi][3] = base[(r0 + 8) * G_APB + kk2 + quad + 4];
                }
            }
            const uint32_t* bb = Bsm + cur * BSTRIDE
                               + ((kk2 >> 1) + quad) * BPITCH;
#pragma unroll
            for (int ni = 0; ni < NT; ni++) {
                int c = warpN * WNC + ni * 8 + grp;
                uint2 bv = *(const uint2*)(bb + 2 * c);
                b[ni][0] = bv.x;
                b[ni][1] = bv.y;
            }
#pragma unroll
            for (int mi = 0; mi < MT; mi++)
#pragma unroll
                for (int ni = 0; ni < NT; ni++)
                    mma_bf16(acc[mi][ni], a[mi], b[ni]);
        }

        int nxt = kb + (ST - 1);
        if (nxt < kb1) issue(nxt, (cur + ST - 1) % ST);
        cp_commit();
        cur = (cur + 1 == ST) ? 0 : cur + 1;
    }

#pragma unroll
    for (int mi = 0; mi < MT; mi++) {
        int r0 = m0 + warpM * 32 + mi * 16 + grp;
#pragma unroll
        for (int ni = 0; ni < NT; ni++) {
            int c = n0 + warpN * WNC + ni * 8 + quad * 2;
            float b0 = 0.f, b1 = 0.f;
            if (EPI) { b0 = bias[c]; b1 = bias[c + 1]; }
#pragma unroll
            for (int h = 0; h < 2; h++) {
                int r = r0 + h * 8;
                if (r >= M) continue;
                float v0 = acc[mi][ni][2 * h + 0];
                float v1 = acc[mi][ni][2 * h + 1];
                if (EPI) {
                    v0 = fmaxf(v0 + b0, 0.f);
                    v1 = fmaxf(v1 + b1, 0.f);
                }
                if (OUTBF) {
                    bf16* Cp = (bf16*)Cv;
                    *(uint32_t*)(Cp + (size_t)r * N + c) = packbf(v0, v1);
                } else {
                    float* Cp = (float*)Cv + (size_t)blockIdx.z * M * N;
                    *(float2*)(Cp + (size_t)r * N + c) = make_float2(v0, v1);
                }
            }
        }
    }
}

// combine KSPLIT split-K partials, relu, write bf16 h0 AND the S1 tail block
__global__ void combine_relu(bf16* __restrict__ h0, bf16* __restrict__ S1,
                             const float* __restrict__ part) {
    int i = blockIdx.x * blockDim.x + threadIdx.x;
    if (i >= NN * INDIM / 2) return;
    float a = 0.f, b = 0.f;
#pragma unroll
    for (int z = 0; z < KSPLIT; z++) {
        float2 s = *(const float2*)(part + 2 * (size_t)i + (size_t)z * NN * INDIM);
        a += s.x;
        b += s.y;
    }
    a = fmaxf(a, 0.f);
    b = fmaxf(b, 0.f);
    uint32_t pk = packbf(a, b);
    *(uint32_t*)(h0 + 2 * (size_t)i) = pk;
    int n = (2 * i) >> 7;
    int col = (2 * i) & 127;
    *(uint32_t*)(S1 + (size_t)n * K1CAT + RR * INDIM + col) = pk;
}

// ---------------- launch ----------------------------------------------------
extern "C" void kernel_launch(void* const* d_in, const int* in_sizes, int n_in,
                              void* d_out, int out_size) {
    const float* x      = (const float*)d_in[0];
    const int*   eidx   = (const int*)  d_in[1];
    const int*   etype  = (const int*)  d_in[2];
    const float* emb    = (const float*)d_in[3];
    const float* comp1  = (const float*)d_in[4];
    const float* basis1 = (const float*)d_in[5];
    const float* root1  = (const float*)d_in[6];
    const float* bias1  = (const float*)d_in[7];
    const float* comp2  = (const float*)d_in[8];
    const float* basis2 = (const float*)d_in[9];
    const float* root2  = (const float*)d_in[10];
    const float* bias2  = (const float*)d_in[11];
    const float* wdec   = (const float*)d_in[12];
    float* out = (float*)d_out;

    const int* srcp = eidx;
    const int* dstp = eidx + EE;

    bf16 *h0b, *S1b, *h1b, *hb2b;
    float *h0p, *invd;
    uint32_t *embp, *W1p, *W2p;
    int *cnt, *off, *bsum, *cur, *esrc, *eoff;
    cudaGetSymbolAddress((void**)&h0b,  g_h0b);
    cudaGetSymbolAddress((void**)&h0p,  g_h0part);
    cudaGetSymbolAddress((void**)&S1b,  g_S1b);
    cudaGetSymbolAddress((void**)&h1b,  g_h1b);
    cudaGetSymbolAddress((void**)&hb2b, g_hb2b);
    cudaGetSymbolAddress((void**)&embp, g_embp);
    cudaGetSymbolAddress((void**)&W1p,  g_W1p);
    cudaGetSymbolAddress((void**)&W2p,  g_W2p);
    cudaGetSymbolAddress((void**)&invd, g_invdeg);
    cudaGetSymbolAddress((void**)&cnt,  g_cnt);
    cudaGetSymbolAddress((void**)&off,  g_off);
    cudaGetSymbolAddress((void**)&bsum, g_bsum);
    cudaGetSymbolAddress((void**)&cur,  g_cur);
    cudaGetSymbolAddress((void**)&esrc, g_esrc);
    cudaGetSymbolAddress((void**)&eoff, g_eoff);

    cudaFuncSetAttribute(gemm_tc<0, 0, 0, 4, 128>,
                         cudaFuncAttributeMaxDynamicSharedMemorySize, SMEM_F32);
    cudaFuncSetAttribute(gemm_tc<1, 1, 1, 5, 64>,
                         cudaFuncAttributeMaxDynamicSharedMemorySize, SMEM_B16_64);
    cudaFuncSetAttribute(gemm_tc<1, 1, 0, 5, 128>,
                         cudaFuncAttributeMaxDynamicSharedMemorySize, SMEM_B16_128);

    cudaStream_t s2;
    cudaEvent_t evF, evJ;
    cudaStreamCreateWithFlags(&s2, cudaStreamNonBlocking);
    cudaEventCreateWithFlags(&evF, cudaEventDisableTiming);
    cudaEventCreateWithFlags(&evJ, cudaEventDisableTiming);

    const int SCAN_BLKS = (NSEG + 1023) / 1024;   // 79

    // submission #1: emb pre-pack (main)
    embconv_p<<<(KB_BIG * 8 * INDIM + 255) / 256, 256>>>(emb, embp);

    cudaEventRecord(evF, 0);
    cudaStreamWaitEvent(s2, evF, 0);

    // submissions #2-3 on side stream
    zeroint<<<(NSEG + 255) / 256, 256, 0, s2>>>(cnt, NSEG);
    countk<<<(EE + 255) / 256, 256, 0, s2>>>(dstp, etype, cnt);

    // submission #4: big GEMM (ncu capture target), 4-stage, f32 partials
    gemm_tc<0, 0, 0, 4, 128><<<dim3((NN + 127) / 128, 1, KSPLIT), 256, SMEM_F32>>>(
        x, embp, h0p, nullptr, NN, INDIM, NN);

    // rest of side stream
    scan1<<<SCAN_BLKS, 1024, 0, s2>>>(cnt, off, bsum);
    scan2<<<1, 128, 0, s2>>>(bsum, SCAN_BLKS);
    scan3<<<SCAN_BLKS, 1024, 0, s2>>>(off, bsum, cur);
    placek<<<(EE + 255) / 256, 256, 0, s2>>>(srcp, dstp, etype, cur, esrc, eoff);
    invdk<<<(NN + 255) / 256, 256, 0, s2>>>(off, invd);
    wbuild_rows_p<<<((K1CAT / 32) * 8 * HID + 255) / 256, 256, 0, s2>>>(
        comp1, basis1, root1, W1p, INDIM, HID);
    wbuild_cols_p<<<((HID / 32) * 8 * N2CAT + 255) / 256, 256, 0, s2>>>(
        comp2, basis2, root2, W2p, HID, EMBD);
    cudaEventRecord(evJ, s2);

    // main stream continues
    combine_relu<<<(NN * INDIM / 2 + 255) / 256, 256>>>(h0b, S1b, h0p);

    cudaStreamWaitEvent(0, evJ, 0);

    // layer 1 (BN=64: grid (79,4)=316 CTAs -> full wave instead of 158)
    gather1<<<(NSEG * 32 + 255) / 256, 256>>>(h0b, off, esrc, invd, S1b);
    gemm_tc<1, 1, 1, 5, 64><<<dim3((NN + 127) / 128, HID / 64, 1), 256, SMEM_B16_64>>>(
        S1b, W1p, h1b, bias1, NN, HID, K1CAT);

    // layer 2 (transform-first)
    gemm_tc<1, 1, 0, 5, 128><<<dim3((NN + 127) / 128, N2CAT / 128, 1), 256, SMEM_B16_128>>>(
        h1b, W2p, hb2b, nullptr, NN, N2CAT, HID);

    // gather 2 + decoder fused
    gather2_dec<<<NN / 8, 256>>>(hb2b, off, eoff, invd, bias2, wdec, out);
}